// round 3
// baseline (speedup 1.0000x reference)
#include <cuda_runtime.h>

#define ND 128
#define HD 256
#define LVLS 4
#define TPB2 256
#define MPAD 132
#define TOTAL_NODES 52400

typedef unsigned long long ull;

__device__ float g_Mt[LVLS][ND * ND];   // Mt[j*ND+k] = (Wv@Wo)[k][j]
__device__ float g_c[LVLS][ND];         // c = bv@Wo
__device__ unsigned char g_mask[TOTAL_NODES];

__device__ __forceinline__ ull ffma2(ull a, ull b, ull c) {
    ull d;
    asm("fma.rn.f32x2 %0, %1, %2, %3;" : "=l"(d) : "l"(a), "l"(b), "l"(c));
    return d;
}
__device__ __forceinline__ float2 upk(ull v) {
    float2 f;
    asm("mov.b64 {%0,%1}, %2;" : "=f"(f.x), "=f"(f.y) : "l"(v));
    return f;
}

// One launch, vectorized x4: flat quarter-edge index -> level -> scatter mask.
__global__ void mark_all_k(const int* __restrict__ t0, const int* __restrict__ t1,
                           const int* __restrict__ t2, const int* __restrict__ t3,
                           int4 ecum4, int4 noff, unsigned char* __restrict__ m) {
    int i = blockIdx.x * blockDim.x + threadIdx.x;   // quarter-edge index
    if (i >= ecum4.w) return;
    const int* t; int off, no;
    if (i < ecum4.x)      { t = t0; off = 0;       no = noff.x; }
    else if (i < ecum4.y) { t = t1; off = ecum4.x; no = noff.y; }
    else if (i < ecum4.z) { t = t2; off = ecum4.y; no = noff.z; }
    else                  { t = t3; off = ecum4.z; no = noff.w; }
    int4 v = reinterpret_cast<const int4*>(t)[i - off];
    unsigned char* mb = m + no;
    mb[v.x] = 1; mb[v.y] = 1; mb[v.z] = 1; mb[v.w] = 1;
}

// Mt = (Wv@Wo)^T, c = bv@Wo. Grid = 4 levels x 32 k-tiles (4 rows each).
__global__ void prep_all_k(const float* __restrict__ Wv, const float* __restrict__ Wo,
                           const float* __restrict__ bv, float* __restrict__ Mt,
                           float* __restrict__ cv) {
    __shared__ float wv_s[4 * 64];
    __shared__ float wo_s[64 * ND];
    const int lvl = blockIdx.x >> 5, kt = blockIdx.x & 31;
    const float* Wvl = Wv + (size_t)lvl * ND * HD;
    const float* Wol = Wo + (size_t)lvl * HD * ND;
    float* Mtl = Mt + (size_t)lvl * ND * ND;
    const int tid = threadIdx.x;            // 256
    const int j = tid & 127, half = tid >> 7;
    float acc0 = 0.f, acc1 = 0.f;

    for (int t0 = 0; t0 < HD; t0 += 64) {
        {
            int r = tid >> 6, c = tid & 63;
            wv_s[tid] = Wvl[(kt * 4 + r) * HD + t0 + c];
        }
        for (int i = tid; i < 64 * ND; i += TPB2) {
            int r = i >> 7, c = i & 127;
            wo_s[i] = Wol[(t0 + r) * ND + c];
        }
        __syncthreads();
        #pragma unroll 8
        for (int t = 0; t < 64; t++) {
            float wo = wo_s[t * ND + j];
            acc0 += wv_s[(half * 2 + 0) * 64 + t] * wo;
            acc1 += wv_s[(half * 2 + 1) * 64 + t] * wo;
        }
        __syncthreads();
    }
    int k0 = kt * 4 + half * 2;
    Mtl[j * ND + k0]     = acc0;
    Mtl[j * ND + k0 + 1] = acc1;
    if (kt == 0 && tid < ND) {
        const float* bvl = bv + (size_t)lvl * HD;
        float cc = 0.f;
        for (int t = 0; t < HD; t++) cc += bvl[t] * Wol[t * ND + tid];
        cv[lvl * ND + tid] = cc;
    }
}

__device__ __forceinline__ int sel4(int4 v, int l) {
    return l == 0 ? v.x : l == 1 ? v.y : l == 2 ? v.z : v.w;
}

// Fused all-level kernel. 256 threads = 128 columns x 2 k-halves.
// M half-column lives in registers (32 ull); smem holds only node rows + partials.
__global__ __launch_bounds__(TPB2, 2)
void level_all_k(const float* __restrict__ n0, const float* __restrict__ n1,
                 const float* __restrict__ n2, const float* __restrict__ n3,
                 const unsigned char* __restrict__ maskb, const float* __restrict__ Mtb,
                 const float* __restrict__ cvb, const float* __restrict__ bob,
                 const float* __restrict__ gb, const float* __restrict__ bb,
                 float* __restrict__ out, int4 bstart, int4 noff, int4 ncnt) {
    extern __shared__ float sm[];
    float* buf  = sm;                       // stage: ND*MPAD ; then rows[0..1023] + part[1024..2047]
    float* c_s  = sm + ND * MPAD;
    float* bo_s = c_s + ND;
    float* g_s  = bo_s + ND;
    float* b_s  = g_s + ND;
    float* mu_s = b_s + ND;                 // 8
    float* rs_s = mu_s + 8;                 // 8
    float* rows = buf;
    float* part = buf + 8 * ND;

    const int tid = threadIdx.x;
    const int col = tid & 127, kh = tid >> 7;
    const int b = blockIdx.x;
    int lvl, b0;
    if (b < bstart.x)      { lvl = 0; b0 = 0; }
    else if (b < bstart.y) { lvl = 1; b0 = bstart.x; }
    else if (b < bstart.z) { lvl = 2; b0 = bstart.y; }
    else                   { lvl = 3; b0 = bstart.z; }

    const float* nodes = lvl == 0 ? n0 : lvl == 1 ? n1 : lvl == 2 ? n2 : n3;
    const int N  = sel4(ncnt, lvl);
    const int nO = sel4(noff, lvl);
    const unsigned char* mask = maskb + nO;
    const float* Mt = Mtb + (size_t)lvl * ND * ND;
    float* outl = out + (size_t)nO * ND;
    const int nodeBase = (b - b0) * 128;    // 16 chunks x 8 nodes

    // Stage full M^T into padded smem (coalesced), then copy half-column to regs.
    for (int i = tid; i < ND * ND; i += TPB2) {
        int j = i >> 7, k = i & 127;
        buf[j * MPAD + k] = Mt[i];
    }
    if (tid < ND) {
        c_s[tid]  = cvb[lvl * ND + tid];
        bo_s[tid] = bob[lvl * ND + tid];
        g_s[tid]  = gb[lvl * ND + tid];
        b_s[tid]  = bb[lvl * ND + tid];
    }
    __syncthreads();

    ull mreg[32];                           // 64 floats: my half of column `col`
    {
        const ull* p = reinterpret_cast<const ull*>(buf + col * MPAD + kh * 64);
        #pragma unroll
        for (int kk = 0; kk < 32; kk++) mreg[kk] = p[kk];
    }
    __syncthreads();                        // staging area now reusable as rows/part

    const ulonglong2* rowsU2 = reinterpret_cast<const ulonglong2*>(rows);
    float4* rows4 = reinterpret_cast<float4*>(rows);
    const float4* nodes4 = reinterpret_cast<const float4*>(nodes);
    const int khoff = kh * 16;              // my half's ulonglong2 offset within a row

    for (int c0 = 0; c0 < 128; c0 += 8) {
        const int base = nodeBase + c0;
        if (base >= N) break;

        // Load 8 node rows (1024 floats) coalesced: 1 float4/thread
        {
            int n = tid >> 5, kk2 = tid & 31;
            int node = base + n;
            rows4[tid] = (node < N) ? nodes4[node * 32 + kk2]
                                    : make_float4(0.f, 0.f, 0.f, 0.f);
        }
        __syncthreads();

        // Matvec over my k-half: 16 x (8 broadcast LDS.128 + 16 FFMA2)
        ull acc[8];
        #pragma unroll
        for (int n = 0; n < 8; n++) acc[n] = 0ull;
        #pragma unroll
        for (int kk = 0; kk < 16; kk++) {
            #pragma unroll
            for (int n = 0; n < 8; n++) {
                ulonglong2 r = rowsU2[n * 32 + khoff + kk];
                acc[n] = ffma2(mreg[2 * kk + 1], r.y, ffma2(mreg[2 * kk], r.x, acc[n]));
            }
        }
        float s[8];
        #pragma unroll
        for (int n = 0; n < 8; n++) { float2 t = upk(acc[n]); s[n] = t.x + t.y; }

        if (kh == 1) {
            #pragma unroll
            for (int n = 0; n < 8; n++) part[n * ND + col] = s[n];
        }
        __syncthreads();

        // kh0 merges halves: x = nodes + bo + mask*(sum + c); write x into rows
        if (kh == 0) {
            #pragma unroll
            for (int n = 0; n < 8; n++) {
                int node = base + n;
                if (node < N) {
                    float x = rows[n * ND + col] + bo_s[col];
                    if (mask[node]) x += s[n] + part[n * ND + col] + c_s[col];
                    rows[n * ND + col] = x;
                }
            }
        }
        __syncthreads();

        // LN stats: warp w -> node w (8 warps, 8 nodes)
        const int wid = tid >> 5, lane = tid & 31;
        {
            float v0 = rows[wid * ND + lane];
            float v1 = rows[wid * ND + lane + 32];
            float v2 = rows[wid * ND + lane + 64];
            float v3 = rows[wid * ND + lane + 96];
            float ssum = v0 + v1 + v2 + v3;
            float s2 = v0 * v0 + v1 * v1 + v2 * v2 + v3 * v3;
            #pragma unroll
            for (int o = 16; o > 0; o >>= 1) {
                ssum += __shfl_xor_sync(0xffffffffu, ssum, o);
                s2   += __shfl_xor_sync(0xffffffffu, s2, o);
            }
            if (lane == 0) {
                float mu = ssum * (1.f / 128.f);
                float var = s2 * (1.f / 128.f) - mu * mu;
                mu_s[wid] = mu;
                rs_s[wid] = rsqrtf(var + 1e-5f);
            }
        }
        __syncthreads();

        // Normalize + affine, coalesced store (all 256 threads, 4 iters)
        #pragma unroll
        for (int r = 0; r < 4; r++) {
            int i = tid + r * TPB2;          // 0..1023
            int n = i >> 7, k = i & 127;
            int node = base + n;
            if (node < N)
                outl[node * ND + k] = (rows[i] - mu_s[n]) * rs_s[n] * g_s[k] + b_s[k];
        }
        __syncthreads();                     // rows/part reused next chunk
    }
}

static const int SMEM_BYTES = (ND * MPAD + 4 * ND + 16) * (int)sizeof(float);

extern "C" void kernel_launch(void* const* d_in, const int* in_sizes, int n_in,
                              void* d_out, int out_size) {
    (void)n_in; (void)out_size;
    int NN[LVLS], NE[LVLS], noffA[LVLS];
    int cumN = 0;
    for (int i = 0; i < LVLS; i++) {
        NN[i] = in_sizes[i * 3] / ND;
        NE[i] = in_sizes[i * 3 + 2] / 2;
        noffA[i] = cumN;
        cumN += NN[i];
    }
    int ec4[LVLS]; int cumE4 = 0;
    for (int i = 0; i < LVLS; i++) { cumE4 += NE[i] / 4; ec4[i] = cumE4; }

    const float* Wv    = (const float*)d_in[16];
    const float* bv    = (const float*)d_in[17];
    const float* Wo    = (const float*)d_in[20];
    const float* bo    = (const float*)d_in[21];
    const float* gamma = (const float*)d_in[22];
    const float* beta  = (const float*)d_in[23];
    float* out = (float*)d_out;

    unsigned char* maskp = nullptr;
    float* Mtp = nullptr;
    float* cp = nullptr;
    cudaGetSymbolAddress((void**)&maskp, g_mask);
    cudaGetSymbolAddress((void**)&Mtp, g_Mt);
    cudaGetSymbolAddress((void**)&cp, g_c);

    cudaFuncSetAttribute(level_all_k, cudaFuncAttributeMaxDynamicSharedMemorySize, SMEM_BYTES);

    // 1) zero mask (memset node in the graph)
    cudaMemsetAsync(maskp, 0, cumN);

    // 2) mark all targets (x4 vectorized), one launch
    const int* t0 = (const int*)d_in[2]  + NE[0];
    const int* t1 = (const int*)d_in[5]  + NE[1];
    const int* t2 = (const int*)d_in[8]  + NE[2];
    const int* t3 = (const int*)d_in[11] + NE[3];
    int4 ecum4 = make_int4(ec4[0], ec4[1], ec4[2], ec4[3]);
    int4 noff = make_int4(noffA[0], noffA[1], noffA[2], noffA[3]);
    mark_all_k<<<(cumE4 + 255) / 256, 256>>>(t0, t1, t2, t3, ecum4, noff, maskp);

    // 3) prep all levels (128 blocks)
    prep_all_k<<<LVLS * 32, TPB2>>>(Wv, Wo, bv, Mtp, cp);

    // 4) fused level kernel
    int bs[LVLS], cumB = 0;
    for (int i = 0; i < LVLS; i++) { cumB += (NN[i] + 127) / 128; bs[i] = cumB; }
    int4 bstart = make_int4(bs[0], bs[1], bs[2], bs[3]);
    int4 ncnt = make_int4(NN[0], NN[1], NN[2], NN[3]);
    level_all_k<<<cumB, TPB2, SMEM_BYTES>>>(
        (const float*)d_in[0], (const float*)d_in[3],
        (const float*)d_in[6], (const float*)d_in[9],
        maskp, Mtp, cp, bo, gamma, beta, out, bstart, noff, ncnt);
}

// round 4
// speedup vs baseline: 1.1529x; 1.1529x over previous
#include <cuda_runtime.h>

#define ND 128
#define HD 256
#define LVLS 4
#define TPB 256
#define NPB 64            // nodes per block tile
#define APAD 132          // float stride (16B-aligned, conflict-managed)
#define TOTAL_NODES 52400
#define MASK_WORDS ((TOTAL_NODES + 31) / 32)

typedef unsigned long long ull;

__device__ float g_M[LVLS][ND * ND];    // row-major: M[k][j] = (Wv@Wo)[k][j]
__device__ float g_c[LVLS][ND];         // c = bv@Wo
__device__ unsigned int g_maskbits[MASK_WORDS];

__device__ __forceinline__ ull ffma2(ull a, ull b, ull c) {
    ull d;
    asm("fma.rn.f32x2 %0, %1, %2, %3;" : "=l"(d) : "l"(a), "l"(b), "l"(c));
    return d;
}
__device__ __forceinline__ float2 upk(ull v) {
    float2 f;
    asm("mov.b64 {%0,%1}, %2;" : "=f"(f.x), "=f"(f.y) : "l"(v));
    return f;
}
__device__ __forceinline__ ull dup2(float a) {
    ull d;
    asm("mov.b64 %0, {%1,%1};" : "=l"(d) : "f"(a));
    return d;
}

// Bit-scatter mark: REDG.OR into bit array, x4 vectorized edge reads.
__global__ void mark_all_k(const int* __restrict__ t0, const int* __restrict__ t1,
                           const int* __restrict__ t2, const int* __restrict__ t3,
                           int4 ecum4, int4 noff, unsigned int* __restrict__ bits) {
    int i = blockIdx.x * blockDim.x + threadIdx.x;   // quarter-edge index
    if (i >= ecum4.w) return;
    const int* t; int off, no;
    if (i < ecum4.x)      { t = t0; off = 0;       no = noff.x; }
    else if (i < ecum4.y) { t = t1; off = ecum4.x; no = noff.y; }
    else if (i < ecum4.z) { t = t2; off = ecum4.y; no = noff.z; }
    else                  { t = t3; off = ecum4.z; no = noff.w; }
    int4 v = reinterpret_cast<const int4*>(t)[i - off];
    int a = no + v.x, b = no + v.y, c = no + v.z, d = no + v.w;
    atomicOr(&bits[a >> 5], 1u << (a & 31));
    atomicOr(&bits[b >> 5], 1u << (b & 31));
    atomicOr(&bits[c >> 5], 1u << (c & 31));
    atomicOr(&bits[d >> 5], 1u << (d & 31));
}

// M = Wv@Wo (row-major), c = bv@Wo. Grid = 4 levels x 32 k-tiles (4 rows each).
__global__ void prep_all_k(const float* __restrict__ Wv, const float* __restrict__ Wo,
                           const float* __restrict__ bv, float* __restrict__ M,
                           float* __restrict__ cv) {
    __shared__ float wv_s[4 * 64];
    __shared__ float wo_s[64 * ND];
    const int lvl = blockIdx.x >> 5, kt = blockIdx.x & 31;
    const float* Wvl = Wv + (size_t)lvl * ND * HD;
    const float* Wol = Wo + (size_t)lvl * HD * ND;
    float* Ml = M + (size_t)lvl * ND * ND;
    const int tid = threadIdx.x;            // 256
    const int j = tid & 127, half = tid >> 7;
    float acc0 = 0.f, acc1 = 0.f;

    for (int t0 = 0; t0 < HD; t0 += 64) {
        {
            int r = tid >> 6, c = tid & 63;
            wv_s[tid] = Wvl[(kt * 4 + r) * HD + t0 + c];
        }
        for (int i = tid; i < 64 * ND; i += TPB) {
            int r = i >> 7, c = i & 127;
            wo_s[i] = Wol[(t0 + r) * ND + c];
        }
        __syncthreads();
        #pragma unroll 8
        for (int t = 0; t < 64; t++) {
            float wo = wo_s[t * ND + j];
            acc0 += wv_s[(half * 2 + 0) * 64 + t] * wo;
            acc1 += wv_s[(half * 2 + 1) * 64 + t] * wo;
        }
        __syncthreads();
    }
    int k0 = kt * 4 + half * 2;
    Ml[(k0 + 0) * ND + j] = acc0;           // row-major, coalesced
    Ml[(k0 + 1) * ND + j] = acc1;
    if (kt == 0 && tid < ND) {
        const float* bvl = bv + (size_t)lvl * HD;
        float cc = 0.f;
        for (int t = 0; t < HD; t++) cc += bvl[t] * Wol[t * ND + tid];
        cv[lvl * ND + tid] = cc;
    }
}

__device__ __forceinline__ int sel4(int4 v, int l) {
    return l == 0 ? v.x : l == 1 ? v.y : l == 2 ? v.z : v.w;
}

// GEMM-tiled fused kernel: 64 nodes x 128 cols per block, 4x8 thread tile,
// ffma2 outer product, fused mask/residual/LayerNorm epilogue.
__global__ __launch_bounds__(TPB, 2)
void level_all_k(const float* __restrict__ n0i, const float* __restrict__ n1i,
                 const float* __restrict__ n2i, const float* __restrict__ n3i,
                 const unsigned int* __restrict__ bits, const float* __restrict__ Mb,
                 const float* __restrict__ cvb, const float* __restrict__ bob,
                 const float* __restrict__ gb, const float* __restrict__ bb,
                 float* __restrict__ out, int4 bstart, int4 noff, int4 ncnt) {
    extern __shared__ float sm[];
    float* M_s = sm;                        // ND * APAD   (M[k][j])
    float* A_s = sm + ND * APAD;            // NPB * APAD  (A[node][k])

    const int tid = threadIdx.x;
    const int b = blockIdx.x;
    int lvl, b0;
    if (b < bstart.x)      { lvl = 0; b0 = 0; }
    else if (b < bstart.y) { lvl = 1; b0 = bstart.x; }
    else if (b < bstart.z) { lvl = 2; b0 = bstart.y; }
    else                   { lvl = 3; b0 = bstart.z; }

    const float* nodes = lvl == 0 ? n0i : lvl == 1 ? n1i : lvl == 2 ? n2i : n3i;
    const int N  = sel4(ncnt, lvl);
    const int nO = sel4(noff, lvl);
    const float* Ml = Mb + (size_t)lvl * ND * ND;
    float* outl = out + (size_t)nO * ND;
    const int nodeBase = (b - b0) * NPB;

    // Stage M (coalesced LDG, conflict-free STS)
    for (int i = tid; i < ND * ND; i += TPB)
        M_s[(i >> 7) * APAD + (i & 127)] = Ml[i];

    // Stage A rows (float4 coalesced; OOB rows zero)
    {
        float4* A_s4 = reinterpret_cast<float4*>(A_s);
        const float4* nodes4 = reinterpret_cast<const float4*>(nodes);
        #pragma unroll
        for (int r = 0; r < 8; r++) {
            int idx = tid + r * TPB;        // 0..2047
            int node = idx >> 5, q = idx & 31;
            int gn = nodeBase + node;
            A_s4[node * 33 + q] = (gn < N) ? nodes4[gn * 32 + q]
                                           : make_float4(0.f, 0.f, 0.f, 0.f);
        }
    }
    __syncthreads();

    const int tc = tid & 15, tr = tid >> 4;
    const int c0 = tc * 8, nloc = tr * 4;

    // Mainloop: C[4 nodes][8 cols] += A[4][k] * M[k][8], k = 0..127
    ull acc[4][4];
    #pragma unroll
    for (int u = 0; u < 4; u++)
        #pragma unroll
        for (int c = 0; c < 4; c++) acc[u][c] = 0ull;

    const float* Ar = A_s + nloc * APAD;
    #pragma unroll 2
    for (int kk = 0; kk < 128; kk += 4) {
        float4 a[4];
        #pragma unroll
        for (int u = 0; u < 4; u++)
            a[u] = *reinterpret_cast<const float4*>(Ar + u * APAD + kk);
        const float* af = reinterpret_cast<const float*>(a);
        #pragma unroll
        for (int t = 0; t < 4; t++) {
            const ulonglong2* mp =
                reinterpret_cast<const ulonglong2*>(M_s + (kk + t) * APAD + c0);
            ulonglong2 m01 = mp[0];
            ulonglong2 m23 = mp[1];
            #pragma unroll
            for (int u = 0; u < 4; u++) {
                ull av2 = dup2(af[u * 4 + t]);
                acc[u][0] = ffma2(av2, m01.x, acc[u][0]);
                acc[u][1] = ffma2(av2, m01.y, acc[u][1]);
                acc[u][2] = ffma2(av2, m23.x, acc[u][2]);
                acc[u][3] = ffma2(av2, m23.y, acc[u][3]);
            }
        }
    }

    // Per-thread params for my 8 columns
    const float4* bo4 = reinterpret_cast<const float4*>(bob + lvl * ND + c0);
    const float4* cv4 = reinterpret_cast<const float4*>(cvb + lvl * ND + c0);
    const float4* g4  = reinterpret_cast<const float4*>(gb + lvl * ND + c0);
    const float4* b4  = reinterpret_cast<const float4*>(bb + lvl * ND + c0);
    float4 boA = bo4[0], boB = bo4[1];
    float4 cvA = cv4[0], cvB = cv4[1];
    float4 gA = g4[0], gB = g4[1];
    float4 bA = b4[0], bB = b4[1];

    // Epilogue: residual + mask + LN (reduce across the 16 tc lanes = half-warp)
    #pragma unroll
    for (int u = 0; u < 4; u++) {
        int node = nloc + u;
        int gn = nodeBase + node;
        int gi = nO + gn;
        float mk = (gn < N) ? (float)((bits[gi >> 5] >> (gi & 31)) & 1u) : 0.f;
        const float4* ar = reinterpret_cast<const float4*>(A_s + node * APAD + c0);
        float4 r0 = ar[0], r1 = ar[1];
        float x[8];
        float2 p;
        p = upk(acc[u][0]); x[0] = r0.x + boA.x + mk * (p.x + cvA.x);
                            x[1] = r0.y + boA.y + mk * (p.y + cvA.y);
        p = upk(acc[u][1]); x[2] = r0.z + boA.z + mk * (p.x + cvA.z);
                            x[3] = r0.w + boA.w + mk * (p.y + cvA.w);
        p = upk(acc[u][2]); x[4] = r1.x + boB.x + mk * (p.x + cvB.x);
                            x[5] = r1.y + boB.y + mk * (p.y + cvB.y);
        p = upk(acc[u][3]); x[6] = r1.z + boB.z + mk * (p.x + cvB.z);
                            x[7] = r1.w + boB.w + mk * (p.y + cvB.w);

        float s = 0.f, s2 = 0.f;
        #pragma unroll
        for (int c = 0; c < 8; c++) { s += x[c]; s2 += x[c] * x[c]; }
        #pragma unroll
        for (int o = 8; o > 0; o >>= 1) {
            s  += __shfl_xor_sync(0xffffffffu, s, o);
            s2 += __shfl_xor_sync(0xffffffffu, s2, o);
        }
        float mu = s * (1.f / 128.f);
        float rs = rsqrtf(s2 * (1.f / 128.f) - mu * mu + 1e-5f);

        if (gn < N) {
            float4 o0, o1;
            o0.x = (x[0] - mu) * rs * gA.x + bA.x;
            o0.y = (x[1] - mu) * rs * gA.y + bA.y;
            o0.z = (x[2] - mu) * rs * gA.z + bA.z;
            o0.w = (x[3] - mu) * rs * gA.w + bA.w;
            o1.x = (x[4] - mu) * rs * gB.x + bB.x;
            o1.y = (x[5] - mu) * rs * gB.y + bB.y;
            o1.z = (x[6] - mu) * rs * gB.z + bB.z;
            o1.w = (x[7] - mu) * rs * gB.w + bB.w;
            float4* op = reinterpret_cast<float4*>(outl + (size_t)gn * ND + c0);
            op[0] = o0;
            op[1] = o1;
        }
    }
}

static const int SMEM_BYTES = (ND + NPB) * APAD * (int)sizeof(float);  // 101376

extern "C" void kernel_launch(void* const* d_in, const int* in_sizes, int n_in,
                              void* d_out, int out_size) {
    (void)n_in; (void)out_size;
    int NN[LVLS], NE[LVLS], noffA[LVLS];
    int cumN = 0;
    for (int i = 0; i < LVLS; i++) {
        NN[i] = in_sizes[i * 3] / ND;
        NE[i] = in_sizes[i * 3 + 2] / 2;
        noffA[i] = cumN;
        cumN += NN[i];
    }
    int ec4[LVLS]; int cumE4 = 0;
    for (int i = 0; i < LVLS; i++) { cumE4 += NE[i] / 4; ec4[i] = cumE4; }

    const float* Wv    = (const float*)d_in[16];
    const float* bv    = (const float*)d_in[17];
    const float* Wo    = (const float*)d_in[20];
    const float* bo    = (const float*)d_in[21];
    const float* gamma = (const float*)d_in[22];
    const float* beta  = (const float*)d_in[23];
    float* out = (float*)d_out;

    unsigned int* bitsp = nullptr;
    float* Mp = nullptr;
    float* cp = nullptr;
    cudaGetSymbolAddress((void**)&bitsp, g_maskbits);
    cudaGetSymbolAddress((void**)&Mp, g_M);
    cudaGetSymbolAddress((void**)&cp, g_c);

    cudaFuncSetAttribute(level_all_k, cudaFuncAttributeMaxDynamicSharedMemorySize, SMEM_BYTES);

    // 1) zero mask bits (tiny)
    cudaMemsetAsync(bitsp, 0, ((cumN + 31) / 32) * sizeof(unsigned int));

    // 2) mark all targets via REDG.OR, one launch
    const int* t0 = (const int*)d_in[2]  + NE[0];
    const int* t1 = (const int*)d_in[5]  + NE[1];
    const int* t2 = (const int*)d_in[8]  + NE[2];
    const int* t3 = (const int*)d_in[11] + NE[3];
    int4 ecum4 = make_int4(ec4[0], ec4[1], ec4[2], ec4[3]);
    int4 noff = make_int4(noffA[0], noffA[1], noffA[2], noffA[3]);
    mark_all_k<<<(cumE4 + 255) / 256, 256>>>(t0, t1, t2, t3, ecum4, noff, bitsp);

    // 3) prep all levels
    prep_all_k<<<LVLS * 32, TPB>>>(Wv, Wo, bv, Mp, cp);

    // 4) fused GEMM+LN kernel
    int bs[LVLS], cumB = 0;
    for (int i = 0; i < LVLS; i++) { cumB += (NN[i] + NPB - 1) / NPB; bs[i] = cumB; }
    int4 bstart = make_int4(bs[0], bs[1], bs[2], bs[3]);
    int4 ncnt = make_int4(NN[0], NN[1], NN[2], NN[3]);
    level_all_k<<<cumB, TPB, SMEM_BYTES>>>(
        (const float*)d_in[0], (const float*)d_in[3],
        (const float*)d_in[6], (const float*)d_in[9],
        bitsp, Mp, cp, bo, gamma, beta, out, bstart, noff, ncnt);
}

// round 5
// speedup vs baseline: 1.6875x; 1.4637x over previous
#include <cuda_runtime.h>

#define ND 128
#define HD 256
#define LVLS 4
#define TPB 256
#define NPB 128           // nodes per block tile
#define TOTAL_NODES 52400

typedef unsigned long long ull;

__device__ float g_M[LVLS][ND * ND];    // row-major: M[k][j] = (Wv@Wo)[k][j]
__device__ float g_c[LVLS][ND];         // c = bv@Wo
__device__ unsigned char g_mask[TOTAL_NODES];

__device__ __forceinline__ ull ffma2(ull a, ull b, ull c) {
    ull d;
    asm("fma.rn.f32x2 %0, %1, %2, %3;" : "=l"(d) : "l"(a), "l"(b), "l"(c));
    return d;
}
__device__ __forceinline__ float2 upk(ull v) {
    float2 f;
    asm("mov.b64 {%0,%1}, %2;" : "=f"(f.x), "=f"(f.y) : "l"(v));
    return f;
}
__device__ __forceinline__ ull dup2(float a) {
    ull d;
    asm("mov.b64 %0, {%1,%1};" : "=l"(d) : "f"(a));
    return d;
}
__device__ __forceinline__ int sel4(int4 v, int l) {
    return l == 0 ? v.x : l == 1 ? v.y : l == 2 ? v.z : v.w;
}

// M = Wv@Wo (row-major), c = bv@Wo; ALSO zeroes the mask byte array.
// Grid = 4 levels x 32 k-tiles (4 rows each) = 128 blocks x 256 threads.
__global__ void prep_all_k(const float* __restrict__ Wv, const float* __restrict__ Wo,
                           const float* __restrict__ bv, float* __restrict__ M,
                           float* __restrict__ cv, unsigned int* __restrict__ m32,
                           int maskWords) {
    // fold mask zeroing in (kernel boundary orders it before level's marking)
    int gt = blockIdx.x * TPB + threadIdx.x;
    if (gt < maskWords) m32[gt] = 0u;

    __shared__ float wv_s[4 * 64];
    __shared__ float wo_s[64 * ND];
    const int lvl = blockIdx.x >> 5, kt = blockIdx.x & 31;
    const float* Wvl = Wv + (size_t)lvl * ND * HD;
    const float* Wol = Wo + (size_t)lvl * HD * ND;
    float* Ml = M + (size_t)lvl * ND * ND;
    const int tid = threadIdx.x;
    const int j = tid & 127, half = tid >> 7;
    float acc0 = 0.f, acc1 = 0.f;

    for (int t0 = 0; t0 < HD; t0 += 64) {
        {
            int r = tid >> 6, c = tid & 63;
            wv_s[tid] = Wvl[(kt * 4 + r) * HD + t0 + c];
        }
        for (int i = tid; i < 64 * ND; i += TPB) {
            int r = i >> 7, c = i & 127;
            wo_s[i] = Wol[(t0 + r) * ND + c];
        }
        __syncthreads();
        #pragma unroll 8
        for (int t = 0; t < 64; t++) {
            float wo = wo_s[t * ND + j];
            acc0 += wv_s[(half * 2 + 0) * 64 + t] * wo;
            acc1 += wv_s[(half * 2 + 1) * 64 + t] * wo;
        }
        __syncthreads();
    }
    int k0 = kt * 4 + half * 2;
    Ml[(k0 + 0) * ND + j] = acc0;
    Ml[(k0 + 1) * ND + j] = acc1;
    if (kt == 0 && tid < ND) {
        const float* bvl = bv + (size_t)lvl * HD;
        float cc = 0.f;
        for (int t = 0; t < HD; t++) cc += bvl[t] * Wol[t * ND + tid];
        cv[lvl * ND + tid] = cc;
    }
}

// Fused: (a) scatter a slice of the edge-target mask (fire-and-forget),
// (b) maskless GEMM tile 128x128 + residual + LN epilogue.
__global__ __launch_bounds__(TPB)
void level_all_k(const float* __restrict__ n0i, const float* __restrict__ n1i,
                 const float* __restrict__ n2i, const float* __restrict__ n3i,
                 const int* __restrict__ t0, const int* __restrict__ t1,
                 const int* __restrict__ t2, const int* __restrict__ t3,
                 int4 ecum4, int epb, unsigned char* __restrict__ mask,
                 const float* __restrict__ Mb, const float* __restrict__ cvb,
                 const float* __restrict__ bob, const float* __restrict__ gb,
                 const float* __restrict__ bb, float* __restrict__ out,
                 int4 bstart, int4 noff, int4 ncnt) {
    extern __shared__ float sm[];
    float* M_s = sm;                        // ND*ND  (M[k][j])
    float* A_s = sm + ND * ND;              // NPB*ND (A[node][k])

    const int tid = threadIdx.x;
    const int b = blockIdx.x;

    // --- mark slice: ~315 quarter-edges per block, byte scatters ---
    {
        int e0 = b * epb;
        int e1 = e0 + epb;
        if (e1 > ecum4.w) e1 = ecum4.w;
        for (int i = e0 + tid; i < e1; i += TPB) {
            const int* t; int off, no;
            if (i < ecum4.x)      { t = t0; off = 0;       no = noff.x; }
            else if (i < ecum4.y) { t = t1; off = ecum4.x; no = noff.y; }
            else if (i < ecum4.z) { t = t2; off = ecum4.y; no = noff.z; }
            else                  { t = t3; off = ecum4.z; no = noff.w; }
            int4 v = reinterpret_cast<const int4*>(t)[i - off];
            unsigned char* mb = mask + no;
            mb[v.x] = 1; mb[v.y] = 1; mb[v.z] = 1; mb[v.w] = 1;
        }
    }

    int lvl, b0;
    if (b < bstart.x)      { lvl = 0; b0 = 0; }
    else if (b < bstart.y) { lvl = 1; b0 = bstart.x; }
    else if (b < bstart.z) { lvl = 2; b0 = bstart.y; }
    else                   { lvl = 3; b0 = bstart.z; }

    const float* nodes = lvl == 0 ? n0i : lvl == 1 ? n1i : lvl == 2 ? n2i : n3i;
    const int N  = sel4(ncnt, lvl);
    const int nO = sel4(noff, lvl);
    const float* Ml = Mb + (size_t)lvl * ND * ND;
    float* outl = out + (size_t)nO * ND;
    const int nodeBase = (b - b0) * NPB;

    // Stage M (identical layout; coalesced LDG + STS)
    for (int i = tid; i < ND * ND; i += TPB) M_s[i] = Ml[i];

    // Stage A rows (float4 coalesced; OOB rows zero)
    {
        float4* A_s4 = reinterpret_cast<float4*>(A_s);
        const float4* nodes4 = reinterpret_cast<const float4*>(nodes);
        #pragma unroll
        for (int r = 0; r < 16; r++) {
            int idx = tid + r * TPB;        // 0..4095
            int node = idx >> 5, q = idx & 31;
            int gn = nodeBase + node;
            A_s4[idx] = (gn < N) ? nodes4[gn * 32 + q]
                                 : make_float4(0.f, 0.f, 0.f, 0.f);
        }
    }
    __syncthreads();

    const int tc = tid & 15, tr = tid >> 4;
    const int c0a = tc * 4, c0b = 64 + tc * 4;   // two conflict-free col chunks
    const int nloc = tr * 8;

    // Mainloop: C[8 nodes][8 cols] += A[8][k] * M[k][8]
    ull acc[8][4];
    #pragma unroll
    for (int u = 0; u < 8; u++)
        #pragma unroll
        for (int c = 0; c < 4; c++) acc[u][c] = 0ull;

    const float* Ar = A_s + nloc * ND;
    #pragma unroll 2
    for (int kk = 0; kk < ND; kk += 4) {
        float4 a[8];
        #pragma unroll
        for (int u = 0; u < 8; u++)
            a[u] = *reinterpret_cast<const float4*>(Ar + u * ND + kk);
        const float* af = reinterpret_cast<const float*>(a);
        #pragma unroll
        for (int t = 0; t < 4; t++) {
            const float* mrow = M_s + (kk + t) * ND;
            ulonglong2 ma = *reinterpret_cast<const ulonglong2*>(mrow + c0a);
            ulonglong2 mb = *reinterpret_cast<const ulonglong2*>(mrow + c0b);
            #pragma unroll
            for (int u = 0; u < 8; u++) {
                ull av2 = dup2(af[u * 4 + t]);
                acc[u][0] = ffma2(av2, ma.x, acc[u][0]);
                acc[u][1] = ffma2(av2, ma.y, acc[u][1]);
                acc[u][2] = ffma2(av2, mb.x, acc[u][2]);
                acc[u][3] = ffma2(av2, mb.y, acc[u][3]);
            }
        }
    }

    // Per-thread params for my 8 columns (maskless: always add agg + c)
    const float* pb = bob + lvl * ND;
    const float* pc = cvb + lvl * ND;
    const float* pg = gb + lvl * ND;
    const float* pp = bb + lvl * ND;
    float4 boA = *reinterpret_cast<const float4*>(pb + c0a);
    float4 boB = *reinterpret_cast<const float4*>(pb + c0b);
    float4 cvA = *reinterpret_cast<const float4*>(pc + c0a);
    float4 cvB = *reinterpret_cast<const float4*>(pc + c0b);
    float4 gA  = *reinterpret_cast<const float4*>(pg + c0a);
    float4 gB  = *reinterpret_cast<const float4*>(pg + c0b);
    float4 bA  = *reinterpret_cast<const float4*>(pp + c0a);
    float4 bB  = *reinterpret_cast<const float4*>(pp + c0b);

    #pragma unroll
    for (int u = 0; u < 8; u++) {
        int node = nloc + u;
        int gn = nodeBase + node;
        float4 r0 = *reinterpret_cast<const float4*>(A_s + node * ND + c0a);
        float4 r1 = *reinterpret_cast<const float4*>(A_s + node * ND + c0b);
        float x[8];
        float2 p;
        p = upk(acc[u][0]); x[0] = r0.x + boA.x + p.x + cvA.x;
                            x[1] = r0.y + boA.y + p.y + cvA.y;
        p = upk(acc[u][1]); x[2] = r0.z + boA.z + p.x + cvA.z;
                            x[3] = r0.w + boA.w + p.y + cvA.w;
        p = upk(acc[u][2]); x[4] = r1.x + boB.x + p.x + cvB.x;
                            x[5] = r1.y + boB.y + p.y + cvB.y;
        p = upk(acc[u][3]); x[6] = r1.z + boB.z + p.x + cvB.z;
                            x[7] = r1.w + boB.w + p.y + cvB.w;

        float s = 0.f, s2 = 0.f;
        #pragma unroll
        for (int c = 0; c < 8; c++) { s += x[c]; s2 += x[c] * x[c]; }
        #pragma unroll
        for (int o = 8; o > 0; o >>= 1) {   // reduce over the 16-lane tc group
            s  += __shfl_xor_sync(0xffffffffu, s, o);
            s2 += __shfl_xor_sync(0xffffffffu, s2, o);
        }
        float mu = s * (1.f / 128.f);
        float rs = rsqrtf(s2 * (1.f / 128.f) - mu * mu + 1e-5f);

        if (gn < N) {
            float4 o0, o1;
            o0.x = (x[0] - mu) * rs * gA.x + bA.x;
            o0.y = (x[1] - mu) * rs * gA.y + bA.y;
            o0.z = (x[2] - mu) * rs * gA.z + bA.z;
            o0.w = (x[3] - mu) * rs * gA.w + bA.w;
            o1.x = (x[4] - mu) * rs * gB.x + bB.x;
            o1.y = (x[5] - mu) * rs * gB.y + bB.y;
            o1.z = (x[6] - mu) * rs * gB.z + bB.z;
            o1.w = (x[7] - mu) * rs * gB.w + bB.w;
            float* op = outl + (size_t)gn * ND;
            *reinterpret_cast<float4*>(op + c0a) = o0;
            *reinterpret_cast<float4*>(op + c0b) = o1;
        }
    }
}

// Rewrite the (rare) unmarked nodes: out = LN(nodes + bo)*gamma + beta.
__global__ void fixup_k(const unsigned char* __restrict__ mask,
                        const float* __restrict__ n0i, const float* __restrict__ n1i,
                        const float* __restrict__ n2i, const float* __restrict__ n3i,
                        const float* __restrict__ bob, const float* __restrict__ gb,
                        const float* __restrict__ bb, float* __restrict__ out,
                        int4 noff, int cumN) {
    int gi = blockIdx.x * blockDim.x + threadIdx.x;
    if (gi >= cumN || mask[gi]) return;
    int lvl = (gi >= noff.w) ? 3 : (gi >= noff.z) ? 2 : (gi >= noff.y) ? 1 : 0;
    const float* nodes = lvl == 0 ? n0i : lvl == 1 ? n1i : lvl == 2 ? n2i : n3i;
    int local = gi - sel4(noff, lvl);
    const float* row = nodes + (size_t)local * ND;
    const float* bo = bob + lvl * ND;
    float s = 0.f, s2 = 0.f;
    for (int c = 0; c < ND; c++) {
        float x = row[c] + bo[c];
        s += x; s2 += x * x;
    }
    float mu = s * (1.f / 128.f);
    float rs = rsqrtf(s2 * (1.f / 128.f) - mu * mu + 1e-5f);
    const float* g = gb + lvl * ND;
    const float* bt = bb + lvl * ND;
    float* op = out + (size_t)gi * ND;
    for (int c = 0; c < ND; c++)
        op[c] = (row[c] + bo[c] - mu) * rs * g[c] + bt[c];
}

static const int SMEM_BYTES = (ND + NPB) * ND * (int)sizeof(float);  // 131072

extern "C" void kernel_launch(void* const* d_in, const int* in_sizes, int n_in,
                              void* d_out, int out_size) {
    (void)n_in; (void)out_size;
    int NN[LVLS], NE[LVLS], noffA[LVLS];
    int cumN = 0;
    for (int i = 0; i < LVLS; i++) {
        NN[i] = in_sizes[i * 3] / ND;
        NE[i] = in_sizes[i * 3 + 2] / 2;
        noffA[i] = cumN;
        cumN += NN[i];
    }
    int ec4[LVLS]; int cumE4 = 0;
    for (int i = 0; i < LVLS; i++) { cumE4 += NE[i] / 4; ec4[i] = cumE4; }

    const float* Wv    = (const float*)d_in[16];
    const float* bv    = (const float*)d_in[17];
    const float* Wo    = (const float*)d_in[20];
    const float* bo    = (const float*)d_in[21];
    const float* gamma = (const float*)d_in[22];
    const float* beta  = (const float*)d_in[23];
    float* out = (float*)d_out;

    unsigned char* maskp = nullptr;
    float* Mp = nullptr;
    float* cp = nullptr;
    cudaGetSymbolAddress((void**)&maskp, g_mask);
    cudaGetSymbolAddress((void**)&Mp, g_M);
    cudaGetSymbolAddress((void**)&cp, g_c);

    cudaFuncSetAttribute(level_all_k, cudaFuncAttributeMaxDynamicSharedMemorySize, SMEM_BYTES);

    // 1) prep: compute M/c for all levels + zero mask bytes
    int maskWords = (cumN + 3) / 4;
    prep_all_k<<<LVLS * 32, TPB>>>(Wv, Wo, bv, Mp, cp,
                                   (unsigned int*)maskp, maskWords);

    // 2) fused level kernel (mark slice + maskless GEMM + LN)
    const int* t0 = (const int*)d_in[2]  + NE[0];
    const int* t1 = (const int*)d_in[5]  + NE[1];
    const int* t2 = (const int*)d_in[8]  + NE[2];
    const int* t3 = (const int*)d_in[11] + NE[3];
    int4 ecum4 = make_int4(ec4[0], ec4[1], ec4[2], ec4[3]);
    int4 noff = make_int4(noffA[0], noffA[1], noffA[2], noffA[3]);

    int bs[LVLS], cumB = 0;
    for (int i = 0; i < LVLS; i++) { cumB += (NN[i] + NPB - 1) / NPB; bs[i] = cumB; }
    int4 bstart = make_int4(bs[0], bs[1], bs[2], bs[3]);
    int4 ncnt = make_int4(NN[0], NN[1], NN[2], NN[3]);
    int epb = (cumE4 + cumB - 1) / cumB;

    level_all_k<<<cumB, TPB, SMEM_BYTES>>>(
        (const float*)d_in[0], (const float*)d_in[3],
        (const float*)d_in[6], (const float*)d_in[9],
        t0, t1, t2, t3, ecum4, epb, maskp,
        Mp, cp, bo, gamma, beta, out, bstart, noff, ncnt);

    // 3) fixup the rare unmarked nodes
    fixup_k<<<(cumN + 255) / 256, 256>>>(
        maskp,
        (const float*)d_in[0], (const float*)d_in[3],
        (const float*)d_in[6], (const float*)d_in[9],
        bo, gamma, beta, out, noff, cumN);
}

// round 6
// speedup vs baseline: 1.9906x; 1.1796x over previous
#include <cuda_runtime.h>

#define ND 128
#define HD 256
#define LVLS 4
#define TPB 256
#define NPB 128           // nodes per block tile
#define TOTAL_NODES 52400

typedef unsigned long long ull;

__device__ float g_M[LVLS][ND * ND];    // row-major: M[k][j] = (Wv@Wo)[k][j]
__device__ float g_c[LVLS][ND];         // c = bv@Wo
__device__ unsigned char g_mask[TOTAL_NODES];

__device__ __forceinline__ ull ffma2(ull a, ull b, ull c) {
    ull d;
    asm("fma.rn.f32x2 %0, %1, %2, %3;" : "=l"(d) : "l"(a), "l"(b), "l"(c));
    return d;
}
__device__ __forceinline__ float2 upk(ull v) {
    float2 f;
    asm("mov.b64 {%0,%1}, %2;" : "=f"(f.x), "=f"(f.y) : "l"(v));
    return f;
}
__device__ __forceinline__ ull dup2(float a) {
    ull d;
    asm("mov.b64 %0, {%1,%1};" : "=l"(d) : "f"(a));
    return d;
}
__device__ __forceinline__ int sel4(int4 v, int l) {
    return l == 0 ? v.x : l == 1 ? v.y : l == 2 ? v.z : v.w;
}

// Sync-free streaming prep: M = Wv@Wo (row-major), c = bv@Wo, + mask zeroing.
// Grid = 4 levels x 32 row-groups (4 M-rows each). 256 thr = 128 cols x 2 t-halves.
__global__ __launch_bounds__(TPB)
void prep_all_k(const float* __restrict__ Wv, const float* __restrict__ Wo,
                const float* __restrict__ bv, float* __restrict__ M,
                float* __restrict__ cv, unsigned int* __restrict__ m32,
                int maskWords) {
    __shared__ float wv_s[4 * HD];          // 4 rows x 256
    __shared__ float part[5 * ND];          // half-1 partials (4 rows + c)

    // fold mask zeroing in (kernel boundary orders it before level's marking)
    int gt = blockIdx.x * TPB + threadIdx.x;
    if (gt < maskWords) m32[gt] = 0u;

    const int lvl = blockIdx.x >> 5, rg = blockIdx.x & 31;
    const int k0 = rg * 4;
    const float* Wvl = Wv + (size_t)lvl * ND * HD;
    const float* Wol = Wo + (size_t)lvl * HD * ND;
    const int tid = threadIdx.x;
    const int j = tid & 127, th = tid >> 7;

    // Stage 4 Wv rows (coalesced)
    #pragma unroll
    for (int r = 0; r < 4; r++)
        wv_s[tid + r * TPB] = Wvl[k0 * HD + tid + r * TPB];
    __syncthreads();

    // Stream Wo over my t-half: 1 coalesced LDG + 4(+1) FMA per iter, no sync.
    const int tBase = th * (HD / 2);
    float acc0 = 0.f, acc1 = 0.f, acc2 = 0.f, acc3 = 0.f, accc = 0.f;
    const bool doC = (rg == 0);
    #pragma unroll 8
    for (int t = 0; t < HD / 2; t++) {
        float wo = Wol[(tBase + t) * ND + j];
        acc0 += wv_s[0 * HD + tBase + t] * wo;
        acc1 += wv_s[1 * HD + tBase + t] * wo;
        acc2 += wv_s[2 * HD + tBase + t] * wo;
        acc3 += wv_s[3 * HD + tBase + t] * wo;
        if (doC) accc += bv[lvl * HD + tBase + t] * wo;
    }

    if (th == 1) {
        part[0 * ND + j] = acc0;
        part[1 * ND + j] = acc1;
        part[2 * ND + j] = acc2;
        part[3 * ND + j] = acc3;
        if (doC) part[4 * ND + j] = accc;
    }
    __syncthreads();
    if (th == 0) {
        float* Ml = M + (size_t)lvl * ND * ND;
        Ml[(k0 + 0) * ND + j] = acc0 + part[0 * ND + j];
        Ml[(k0 + 1) * ND + j] = acc1 + part[1 * ND + j];
        Ml[(k0 + 2) * ND + j] = acc2 + part[2 * ND + j];
        Ml[(k0 + 3) * ND + j] = acc3 + part[3 * ND + j];
        if (doC) cv[lvl * ND + j] = accc + part[4 * ND + j];
    }
}

// Fused: (a) scatter a slice of the edge-target mask (fire-and-forget),
// (b) maskless GEMM tile 128x128 + residual + LN epilogue.
__global__ __launch_bounds__(TPB)
void level_all_k(const float* __restrict__ n0i, const float* __restrict__ n1i,
                 const float* __restrict__ n2i, const float* __restrict__ n3i,
                 const int* __restrict__ t0, const int* __restrict__ t1,
                 const int* __restrict__ t2, const int* __restrict__ t3,
                 int4 ecum4, int epb, unsigned char* __restrict__ mask,
                 const float* __restrict__ Mb, const float* __restrict__ cvb,
                 const float* __restrict__ bob, const float* __restrict__ gb,
                 const float* __restrict__ bb, float* __restrict__ out,
                 int4 bstart, int4 noff, int4 ncnt) {
    extern __shared__ float sm[];
    float* M_s = sm;                        // ND*ND  (M[k][j])
    float* A_s = sm + ND * ND;              // NPB*ND (A[node][k])

    const int tid = threadIdx.x;
    const int b = blockIdx.x;

    // --- mark slice: fire-and-forget byte scatters, drains under the GEMM ---
    {
        int e0 = b * epb;
        int e1 = e0 + epb;
        if (e1 > ecum4.w) e1 = ecum4.w;
        for (int i = e0 + tid; i < e1; i += TPB) {
            const int* t; int off, no;
            if (i < ecum4.x)      { t = t0; off = 0;       no = noff.x; }
            else if (i < ecum4.y) { t = t1; off = ecum4.x; no = noff.y; }
            else if (i < ecum4.z) { t = t2; off = ecum4.y; no = noff.z; }
            else                  { t = t3; off = ecum4.z; no = noff.w; }
            int4 v = reinterpret_cast<const int4*>(t)[i - off];
            unsigned char* mb = mask + no;
            mb[v.x] = 1; mb[v.y] = 1; mb[v.z] = 1; mb[v.w] = 1;
        }
    }

    int lvl, b0;
    if (b < bstart.x)      { lvl = 0; b0 = 0; }
    else if (b < bstart.y) { lvl = 1; b0 = bstart.x; }
    else if (b < bstart.z) { lvl = 2; b0 = bstart.y; }
    else                   { lvl = 3; b0 = bstart.z; }

    const float* nodes = lvl == 0 ? n0i : lvl == 1 ? n1i : lvl == 2 ? n2i : n3i;
    const int N  = sel4(ncnt, lvl);
    const int nO = sel4(noff, lvl);
    const float* Ml = Mb + (size_t)lvl * ND * ND;
    float* outl = out + (size_t)nO * ND;
    const int nodeBase = (b - b0) * NPB;

    // Stage M with float4 (16 LDG.128+STS.128 per thread)
    {
        float4* M_s4 = reinterpret_cast<float4*>(M_s);
        const float4* Ml4 = reinterpret_cast<const float4*>(Ml);
        #pragma unroll
        for (int r = 0; r < 16; r++)
            M_s4[tid + r * TPB] = Ml4[tid + r * TPB];
    }

    // Stage A rows (float4 coalesced; OOB rows zero)
    {
        float4* A_s4 = reinterpret_cast<float4*>(A_s);
        const float4* nodes4 = reinterpret_cast<const float4*>(nodes);
        #pragma unroll
        for (int r = 0; r < 16; r++) {
            int idx = tid + r * TPB;        // 0..4095
            int node = idx >> 5, q = idx & 31;
            int gn = nodeBase + node;
            A_s4[idx] = (gn < N) ? nodes4[gn * 32 + q]
                                 : make_float4(0.f, 0.f, 0.f, 0.f);
        }
    }
    __syncthreads();

    const int tc = tid & 15, tr = tid >> 4;
    const int c0a = tc * 4, c0b = 64 + tc * 4;   // two conflict-free col chunks
    const int nloc = tr * 8;

    // Mainloop: C[8 nodes][8 cols] += A[8][k] * M[k][8]
    ull acc[8][4];
    #pragma unroll
    for (int u = 0; u < 8; u++)
        #pragma unroll
        for (int c = 0; c < 4; c++) acc[u][c] = 0ull;

    const float* Ar = A_s + nloc * ND;
    #pragma unroll 2
    for (int kk = 0; kk < ND; kk += 4) {
        float4 a[8];
        #pragma unroll
        for (int u = 0; u < 8; u++)
            a[u] = *reinterpret_cast<const float4*>(Ar + u * ND + kk);
        const float* af = reinterpret_cast<const float*>(a);
        #pragma unroll
        for (int t = 0; t < 4; t++) {
            const float* mrow = M_s + (kk + t) * ND;
            ulonglong2 ma = *reinterpret_cast<const ulonglong2*>(mrow + c0a);
            ulonglong2 mb = *reinterpret_cast<const ulonglong2*>(mrow + c0b);
            #pragma unroll
            for (int u = 0; u < 8; u++) {
                ull av2 = dup2(af[u * 4 + t]);
                acc[u][0] = ffma2(av2, ma.x, acc[u][0]);
                acc[u][1] = ffma2(av2, ma.y, acc[u][1]);
                acc[u][2] = ffma2(av2, mb.x, acc[u][2]);
                acc[u][3] = ffma2(av2, mb.y, acc[u][3]);
            }
        }
    }

    // Per-thread params for my 8 columns (maskless: always add agg + c)
    const float* pb = bob + lvl * ND;
    const float* pc = cvb + lvl * ND;
    const float* pg = gb + lvl * ND;
    const float* pp = bb + lvl * ND;
    float4 boA = *reinterpret_cast<const float4*>(pb + c0a);
    float4 boB = *reinterpret_cast<const float4*>(pb + c0b);
    float4 cvA = *reinterpret_cast<const float4*>(pc + c0a);
    float4 cvB = *reinterpret_cast<const float4*>(pc + c0b);
    float4 gA  = *reinterpret_cast<const float4*>(pg + c0a);
    float4 gB  = *reinterpret_cast<const float4*>(pg + c0b);
    float4 bA  = *reinterpret_cast<const float4*>(pp + c0a);
    float4 bB  = *reinterpret_cast<const float4*>(pp + c0b);

    #pragma unroll
    for (int u = 0; u < 8; u++) {
        int node = nloc + u;
        int gn = nodeBase + node;
        float4 r0 = *reinterpret_cast<const float4*>(A_s + node * ND + c0a);
        float4 r1 = *reinterpret_cast<const float4*>(A_s + node * ND + c0b);
        float x[8];
        float2 p;
        p = upk(acc[u][0]); x[0] = r0.x + boA.x + p.x + cvA.x;
                            x[1] = r0.y + boA.y + p.y + cvA.y;
        p = upk(acc[u][1]); x[2] = r0.z + boA.z + p.x + cvA.z;
                            x[3] = r0.w + boA.w + p.y + cvA.w;
        p = upk(acc[u][2]); x[4] = r1.x + boB.x + p.x + cvB.x;
                            x[5] = r1.y + boB.y + p.y + cvB.y;
        p = upk(acc[u][3]); x[6] = r1.z + boB.z + p.x + cvB.z;
                            x[7] = r1.w + boB.w + p.y + cvB.w;

        float s = 0.f, s2 = 0.f;
        #pragma unroll
        for (int c = 0; c < 8; c++) { s += x[c]; s2 += x[c] * x[c]; }
        #pragma unroll
        for (int o = 8; o > 0; o >>= 1) {   // reduce over the 16-lane tc group
            s  += __shfl_xor_sync(0xffffffffu, s, o);
            s2 += __shfl_xor_sync(0xffffffffu, s2, o);
        }
        float mu = s * (1.f / 128.f);
        float rs = rsqrtf(s2 * (1.f / 128.f) - mu * mu + 1e-5f);

        if (gn < N) {
            float4 o0, o1;
            o0.x = (x[0] - mu) * rs * gA.x + bA.x;
            o0.y = (x[1] - mu) * rs * gA.y + bA.y;
            o0.z = (x[2] - mu) * rs * gA.z + bA.z;
            o0.w = (x[3] - mu) * rs * gA.w + bA.w;
            o1.x = (x[4] - mu) * rs * gB.x + bB.x;
            o1.y = (x[5] - mu) * rs * gB.y + bB.y;
            o1.z = (x[6] - mu) * rs * gB.z + bB.z;
            o1.w = (x[7] - mu) * rs * gB.w + bB.w;
            float* op = outl + (size_t)gn * ND;
            *reinterpret_cast<float4*>(op + c0a) = o0;
            *reinterpret_cast<float4*>(op + c0b) = o1;
        }
    }
}

// Rewrite the (rare) unmarked nodes: out = LN(nodes + bo)*gamma + beta.
__global__ void fixup_k(const unsigned char* __restrict__ mask,
                        const float* __restrict__ n0i, const float* __restrict__ n1i,
                        const float* __restrict__ n2i, const float* __restrict__ n3i,
                        const float* __restrict__ bob, const float* __restrict__ gb,
                        const float* __restrict__ bb, float* __restrict__ out,
                        int4 noff, int cumN) {
    int gi = blockIdx.x * blockDim.x + threadIdx.x;
    if (gi >= cumN || mask[gi]) return;
    int lvl = (gi >= noff.w) ? 3 : (gi >= noff.z) ? 2 : (gi >= noff.y) ? 1 : 0;
    const float* nodes = lvl == 0 ? n0i : lvl == 1 ? n1i : lvl == 2 ? n2i : n3i;
    int local = gi - sel4(noff, lvl);
    const float* row = nodes + (size_t)local * ND;
    const float* bo = bob + lvl * ND;
    float s = 0.f, s2 = 0.f;
    for (int c = 0; c < ND; c++) {
        float x = row[c] + bo[c];
        s += x; s2 += x * x;
    }
    float mu = s * (1.f / 128.f);
    float rs = rsqrtf(s2 * (1.f / 128.f) - mu * mu + 1e-5f);
    const float* g = gb + lvl * ND;
    const float* bt = bb + lvl * ND;
    float* op = out + (size_t)gi * ND;
    for (int c = 0; c < ND; c++)
        op[c] = (row[c] + bo[c] - mu) * rs * g[c] + bt[c];
}

static const int SMEM_BYTES = (ND + NPB) * ND * (int)sizeof(float);  // 131072

extern "C" void kernel_launch(void* const* d_in, const int* in_sizes, int n_in,
                              void* d_out, int out_size) {
    (void)n_in; (void)out_size;
    int NN[LVLS], NE[LVLS], noffA[LVLS];
    int cumN = 0;
    for (int i = 0; i < LVLS; i++) {
        NN[i] = in_sizes[i * 3] / ND;
        NE[i] = in_sizes[i * 3 + 2] / 2;
        noffA[i] = cumN;
        cumN += NN[i];
    }
    int ec4[LVLS]; int cumE4 = 0;
    for (int i = 0; i < LVLS; i++) { cumE4 += NE[i] / 4; ec4[i] = cumE4; }

    const float* Wv    = (const float*)d_in[16];
    const float* bv    = (const float*)d_in[17];
    const float* Wo    = (const float*)d_in[20];
    const float* bo    = (const float*)d_in[21];
    const float* gamma = (const float*)d_in[22];
    const float* beta  = (const float*)d_in[23];
    float* out = (float*)d_out;

    unsigned char* maskp = nullptr;
    float* Mp = nullptr;
    float* cp = nullptr;
    cudaGetSymbolAddress((void**)&maskp, g_mask);
    cudaGetSymbolAddress((void**)&Mp, g_M);
    cudaGetSymbolAddress((void**)&cp, g_c);

    cudaFuncSetAttribute(level_all_k, cudaFuncAttributeMaxDynamicSharedMemorySize, SMEM_BYTES);

    // 1) prep: compute M/c for all levels + zero mask bytes
    int maskWords = (cumN + 3) / 4;
    prep_all_k<<<LVLS * 32, TPB>>>(Wv, Wo, bv, Mp, cp,
                                   (unsigned int*)maskp, maskWords);

    // 2) fused level kernel (mark slice + maskless GEMM + LN)
    const int* t0 = (const int*)d_in[2]  + NE[0];
    const int* t1 = (const int*)d_in[5]  + NE[1];
    const int* t2 = (const int*)d_in[8]  + NE[2];
    const int* t3 = (const int*)d_in[11] + NE[3];
    int4 ecum4 = make_int4(ec4[0], ec4[1], ec4[2], ec4[3]);
    int4 noff = make_int4(noffA[0], noffA[1], noffA[2], noffA[3]);

    int bs[LVLS], cumB = 0;
    for (int i = 0; i < LVLS; i++) { cumB += (NN[i] + NPB - 1) / NPB; bs[i] = cumB; }
    int4 bstart = make_int4(bs[0], bs[1], bs[2], bs[3]);
    int4 ncnt = make_int4(NN[0], NN[1], NN[2], NN[3]);
    int epb = (cumE4 + cumB - 1) / cumB;

    level_all_k<<<cumB, TPB, SMEM_BYTES>>>(
        (const float*)d_in[0], (const float*)d_in[3],
        (const float*)d_in[6], (const float*)d_in[9],
        t0, t1, t2, t3, ecum4, epb, maskp,
        Mp, cp, bo, gamma, beta, out, bstart, noff, ncnt);

    // 3) fixup the rare unmarked nodes
    fixup_k<<<(cumN + 255) / 256, 256>>>(
        maskp,
        (const float*)d_in[0], (const float*)d_in[3],
        (const float*)d_in[6], (const float*)d_in[9],
        bo, gamma, beta, out, noff, cumN);
}

// round 7
// speedup vs baseline: 2.1586x; 1.0844x over previous
#include <cuda_runtime.h>

#define ND 128
#define HD 256
#define LVLS 4
#define TPB 256
#define NPB 128           // nodes per block tile
#define TOTAL_NODES 52400

typedef unsigned long long ull;

__device__ float g_M[LVLS][ND * ND];    // row-major: M[k][j] = (Wv@Wo)[k][j]
__device__ float g_c[LVLS][ND];         // c = bv@Wo
__device__ unsigned char g_mask[TOTAL_NODES];

__device__ __forceinline__ ull ffma2(ull a, ull b, ull c) {
    ull d;
    asm("fma.rn.f32x2 %0, %1, %2, %3;" : "=l"(d) : "l"(a), "l"(b), "l"(c));
    return d;
}
__device__ __forceinline__ float2 upk(ull v) {
    float2 f;
    asm("mov.b64 {%0,%1}, %2;" : "=f"(f.x), "=f"(f.y) : "l"(v));
    return f;
}
__device__ __forceinline__ ull dup2(float a) {
    ull d;
    asm("mov.b64 %0, {%1,%1};" : "=l"(d) : "f"(a));
    return d;
}
__device__ __forceinline__ int sel4(int4 v, int l) {
    return l == 0 ? v.x : l == 1 ? v.y : l == 2 ? v.z : v.w;
}

// Prep: M = Wv@Wo (row-major), c = bv@Wo, + mask zeroing.
// Grid = 4 levels x 64 row-groups (2 M-rows each) = 256 blocks.
// 256 thr = 128 cols x 2 t-halves. Mainloop: explicit 16-wide load batches, no branches.
__global__ __launch_bounds__(TPB)
void prep_all_k(const float* __restrict__ Wv, const float* __restrict__ Wo,
                const float* __restrict__ bv, float* __restrict__ M,
                float* __restrict__ cv, unsigned int* __restrict__ m32,
                int maskWords) {
    __shared__ float wv_s[2 * HD];          // 2 Wv rows
    __shared__ float bv_s[HD];
    __shared__ float part[3 * ND];          // half-1 partials (2 rows + c)

    // fold mask zeroing in (kernel boundary orders it before level's marking)
    int gt = blockIdx.x * TPB + threadIdx.x;
    if (gt < maskWords) m32[gt] = 0u;

    const int lvl = blockIdx.x >> 6, rg = blockIdx.x & 63;
    const int k0 = rg * 2;
    const float* Wvl = Wv + (size_t)lvl * ND * HD;
    const float* Wol = Wo + (size_t)lvl * HD * ND;
    const int tid = threadIdx.x;
    const int j = tid & 127, th = tid >> 7;

    // Stage 2 Wv rows + bv (coalesced)
    wv_s[tid]       = Wvl[k0 * HD + tid];
    wv_s[tid + TPB] = Wvl[k0 * HD + tid + TPB];
    bv_s[tid < HD ? tid : 0] = bv[lvl * HD + (tid < HD ? tid : 0)];
    __syncthreads();

    // Stream Wo over my t-half in explicit 16-wide batches (MLP=16, branch-free).
    const int tBase = th * (HD / 2);
    float acc0 = 0.f, acc1 = 0.f, accc = 0.f;
    #pragma unroll
    for (int tt = 0; tt < HD / 2; tt += 16) {
        float wo[16];
        #pragma unroll
        for (int u = 0; u < 16; u++)
            wo[u] = Wol[(tBase + tt + u) * ND + j];
        #pragma unroll
        for (int u = 0; u < 16; u++) {
            int t = tBase + tt + u;
            acc0 += wv_s[t] * wo[u];
            acc1 += wv_s[HD + t] * wo[u];
            accc += bv_s[t] * wo[u];
        }
    }

    if (th == 1) {
        part[0 * ND + j] = acc0;
        part[1 * ND + j] = acc1;
        part[2 * ND + j] = accc;
    }
    __syncthreads();
    if (th == 0) {
        float* Ml = M + (size_t)lvl * ND * ND;
        Ml[(k0 + 0) * ND + j] = acc0 + part[0 * ND + j];
        Ml[(k0 + 1) * ND + j] = acc1 + part[1 * ND + j];
        if (rg == 0) cv[lvl * ND + j] = accc + part[2 * ND + j];
    }
}

// Fused: (a) scatter a slice of the edge-target mask (fire-and-forget),
// (b) maskless GEMM tile 128x128 + residual + LN epilogue.
__global__ __launch_bounds__(TPB)
void level_all_k(const float* __restrict__ n0i, const float* __restrict__ n1i,
                 const float* __restrict__ n2i, const float* __restrict__ n3i,
                 const int* __restrict__ t0, const int* __restrict__ t1,
                 const int* __restrict__ t2, const int* __restrict__ t3,
                 int4 ecum4, int epb, unsigned char* __restrict__ mask,
                 const float* __restrict__ Mb, const float* __restrict__ cvb,
                 const float* __restrict__ bob, const float* __restrict__ gb,
                 const float* __restrict__ bb, float* __restrict__ out,
                 int4 bstart, int4 noff, int4 ncnt) {
    extern __shared__ float sm[];
    float* M_s = sm;                        // ND*ND  (M[k][j])
    float* A_s = sm + ND * ND;              // NPB*ND (A[node][k])

    const int tid = threadIdx.x;
    const int b = blockIdx.x;

    // --- mark slice: fire-and-forget byte scatters, drains under the GEMM ---
    {
        int e0 = b * epb;
        int e1 = e0 + epb;
        if (e1 > ecum4.w) e1 = ecum4.w;
        for (int i = e0 + tid; i < e1; i += TPB) {
            const int* t; int off, no;
            if (i < ecum4.x)      { t = t0; off = 0;       no = noff.x; }
            else if (i < ecum4.y) { t = t1; off = ecum4.x; no = noff.y; }
            else if (i < ecum4.z) { t = t2; off = ecum4.y; no = noff.z; }
            else                  { t = t3; off = ecum4.z; no = noff.w; }
            int4 v = reinterpret_cast<const int4*>(t)[i - off];
            unsigned char* mb = mask + no;
            mb[v.x] = 1; mb[v.y] = 1; mb[v.z] = 1; mb[v.w] = 1;
        }
    }

    int lvl, b0;
    if (b < bstart.x)      { lvl = 0; b0 = 0; }
    else if (b < bstart.y) { lvl = 1; b0 = bstart.x; }
    else if (b < bstart.z) { lvl = 2; b0 = bstart.y; }
    else                   { lvl = 3; b0 = bstart.z; }

    const float* nodes = lvl == 0 ? n0i : lvl == 1 ? n1i : lvl == 2 ? n2i : n3i;
    const int N  = sel4(ncnt, lvl);
    const int nO = sel4(noff, lvl);
    const float* Ml = Mb + (size_t)lvl * ND * ND;
    float* outl = out + (size_t)nO * ND;
    const int nodeBase = (b - b0) * NPB;

    // Stage M with float4 (16 LDG.128+STS.128 per thread)
    {
        float4* M_s4 = reinterpret_cast<float4*>(M_s);
        const float4* Ml4 = reinterpret_cast<const float4*>(Ml);
        #pragma unroll
        for (int r = 0; r < 16; r++)
            M_s4[tid + r * TPB] = Ml4[tid + r * TPB];
    }

    // Stage A rows (float4 coalesced; OOB rows zero)
    {
        float4* A_s4 = reinterpret_cast<float4*>(A_s);
        const float4* nodes4 = reinterpret_cast<const float4*>(nodes);
        #pragma unroll
        for (int r = 0; r < 16; r++) {
            int idx = tid + r * TPB;        // 0..4095
            int node = idx >> 5, q = idx & 31;
            int gn = nodeBase + node;
            A_s4[idx] = (gn < N) ? nodes4[gn * 32 + q]
                                 : make_float4(0.f, 0.f, 0.f, 0.f);
        }
    }
    __syncthreads();

    const int tc = tid & 15, tr = tid >> 4;
    const int c0a = tc * 4, c0b = 64 + tc * 4;   // two conflict-free col chunks
    const int nloc = tr * 8;

    // Mainloop: C[8 nodes][8 cols] += A[8][k] * M[k][8]
    ull acc[8][4];
    #pragma unroll
    for (int u = 0; u < 8; u++)
        #pragma unroll
        for (int c = 0; c < 4; c++) acc[u][c] = 0ull;

    const float* Ar = A_s + nloc * ND;
    #pragma unroll 2
    for (int kk = 0; kk < ND; kk += 4) {
        float4 a[8];
        #pragma unroll
        for (int u = 0; u < 8; u++)
            a[u] = *reinterpret_cast<const float4*>(Ar + u * ND + kk);
        const float* af = reinterpret_cast<const float*>(a);
        #pragma unroll
        for (int t = 0; t < 4; t++) {
            const float* mrow = M_s + (kk + t) * ND;
            ulonglong2 ma = *reinterpret_cast<const ulonglong2*>(mrow + c0a);
            ulonglong2 mb = *reinterpret_cast<const ulonglong2*>(mrow + c0b);
            #pragma unroll
            for (int u = 0; u < 8; u++) {
                ull av2 = dup2(af[u * 4 + t]);
                acc[u][0] = ffma2(av2, ma.x, acc[u][0]);
                acc[u][1] = ffma2(av2, ma.y, acc[u][1]);
                acc[u][2] = ffma2(av2, mb.x, acc[u][2]);
                acc[u][3] = ffma2(av2, mb.y, acc[u][3]);
            }
        }
    }

    // Per-thread params for my 8 columns (maskless: always add agg + c)
    const float* pb = bob + lvl * ND;
    const float* pc = cvb + lvl * ND;
    const float* pg = gb + lvl * ND;
    const float* pp = bb + lvl * ND;
    float4 boA = *reinterpret_cast<const float4*>(pb + c0a);
    float4 boB = *reinterpret_cast<const float4*>(pb + c0b);
    float4 cvA = *reinterpret_cast<const float4*>(pc + c0a);
    float4 cvB = *reinterpret_cast<const float4*>(pc + c0b);
    float4 gA  = *reinterpret_cast<const float4*>(pg + c0a);
    float4 gB  = *reinterpret_cast<const float4*>(pg + c0b);
    float4 bA  = *reinterpret_cast<const float4*>(pp + c0a);
    float4 bB  = *reinterpret_cast<const float4*>(pp + c0b);

    #pragma unroll
    for (int u = 0; u < 8; u++) {
        int node = nloc + u;
        int gn = nodeBase + node;
        float4 r0 = *reinterpret_cast<const float4*>(A_s + node * ND + c0a);
        float4 r1 = *reinterpret_cast<const float4*>(A_s + node * ND + c0b);
        float x[8];
        float2 p;
        p = upk(acc[u][0]); x[0] = r0.x + boA.x + p.x + cvA.x;
                            x[1] = r0.y + boA.y + p.y + cvA.y;
        p = upk(acc[u][1]); x[2] = r0.z + boA.z + p.x + cvA.z;
                            x[3] = r0.w + boA.w + p.y + cvA.w;
        p = upk(acc[u][2]); x[4] = r1.x + boB.x + p.x + cvB.x;
                            x[5] = r1.y + boB.y + p.y + cvB.y;
        p = upk(acc[u][3]); x[6] = r1.z + boB.z + p.x + cvB.z;
                            x[7] = r1.w + boB.w + p.y + cvB.w;

        float s = 0.f, s2 = 0.f;
        #pragma unroll
        for (int c = 0; c < 8; c++) { s += x[c]; s2 += x[c] * x[c]; }
        #pragma unroll
        for (int o = 8; o > 0; o >>= 1) {   // reduce over the 16-lane tc group
            s  += __shfl_xor_sync(0xffffffffu, s, o);
            s2 += __shfl_xor_sync(0xffffffffu, s2, o);
        }
        float mu = s * (1.f / 128.f);
        float rs = rsqrtf(s2 * (1.f / 128.f) - mu * mu + 1e-5f);

        if (gn < N) {
            float4 o0, o1;
            o0.x = (x[0] - mu) * rs * gA.x + bA.x;
            o0.y = (x[1] - mu) * rs * gA.y + bA.y;
            o0.z = (x[2] - mu) * rs * gA.z + bA.z;
            o0.w = (x[3] - mu) * rs * gA.w + bA.w;
            o1.x = (x[4] - mu) * rs * gB.x + bB.x;
            o1.y = (x[5] - mu) * rs * gB.y + bB.y;
            o1.z = (x[6] - mu) * rs * gB.z + bB.z;
            o1.w = (x[7] - mu) * rs * gB.w + bB.w;
            float* op = outl + (size_t)gn * ND;
            *reinterpret_cast<float4*>(op + c0a) = o0;
            *reinterpret_cast<float4*>(op + c0b) = o1;
        }
    }
}

// Rewrite the (rare) unmarked nodes: out = LN(nodes + bo)*gamma + beta.
__global__ void fixup_k(const unsigned char* __restrict__ mask,
                        const float* __restrict__ n0i, const float* __restrict__ n1i,
                        const float* __restrict__ n2i, const float* __restrict__ n3i,
                        const float* __restrict__ bob, const float* __restrict__ gb,
                        const float* __restrict__ bb, float* __restrict__ out,
                        int4 noff, int cumN) {
    int gi = blockIdx.x * blockDim.x + threadIdx.x;
    if (gi >= cumN || mask[gi]) return;
    int lvl = (gi >= noff.w) ? 3 : (gi >= noff.z) ? 2 : (gi >= noff.y) ? 1 : 0;
    const float* nodes = lvl == 0 ? n0i : lvl == 1 ? n1i : lvl == 2 ? n2i : n3i;
    int local = gi - sel4(noff, lvl);
    const float* row = nodes + (size_t)local * ND;
    const float* bo = bob + lvl * ND;
    float s = 0.f, s2 = 0.f;
    for (int c = 0; c < ND; c++) {
        float x = row[c] + bo[c];
        s += x; s2 += x * x;
    }
    float mu = s * (1.f / 128.f);
    float rs = rsqrtf(s2 * (1.f / 128.f) - mu * mu + 1e-5f);
    const float* g = gb + lvl * ND;
    const float* bt = bb + lvl * ND;
    float* op = out + (size_t)gi * ND;
    for (int c = 0; c < ND; c++)
        op[c] = (row[c] + bo[c] - mu) * rs * g[c] + bt[c];
}

static const int SMEM_BYTES = (ND + NPB) * ND * (int)sizeof(float);  // 131072

extern "C" void kernel_launch(void* const* d_in, const int* in_sizes, int n_in,
                              void* d_out, int out_size) {
    (void)n_in; (void)out_size;
    int NN[LVLS], NE[LVLS], noffA[LVLS];
    int cumN = 0;
    for (int i = 0; i < LVLS; i++) {
        NN[i] = in_sizes[i * 3] / ND;
        NE[i] = in_sizes[i * 3 + 2] / 2;
        noffA[i] = cumN;
        cumN += NN[i];
    }
    int ec4[LVLS]; int cumE4 = 0;
    for (int i = 0; i < LVLS; i++) { cumE4 += NE[i] / 4; ec4[i] = cumE4; }

    const float* Wv    = (const float*)d_in[16];
    const float* bv    = (const float*)d_in[17];
    const float* Wo    = (const float*)d_in[20];
    const float* bo    = (const float*)d_in[21];
    const float* gamma = (const float*)d_in[22];
    const float* beta  = (const float*)d_in[23];
    float* out = (float*)d_out;

    unsigned char* maskp = nullptr;
    float* Mp = nullptr;
    float* cp = nullptr;
    cudaGetSymbolAddress((void**)&maskp, g_mask);
    cudaGetSymbolAddress((void**)&Mp, g_M);
    cudaGetSymbolAddress((void**)&cp, g_c);

    cudaFuncSetAttribute(level_all_k, cudaFuncAttributeMaxDynamicSharedMemorySize, SMEM_BYTES);

    // 1) prep: compute M/c for all levels + zero mask bytes
    int maskWords = (cumN + 3) / 4;
    prep_all_k<<<LVLS * 64, TPB>>>(Wv, Wo, bv, Mp, cp,
                                   (unsigned int*)maskp, maskWords);

    // 2) fused level kernel (mark slice + maskless GEMM + LN)
    const int* t0 = (const int*)d_in[2]  + NE[0];
    const int* t1 = (const int*)d_in[5]  + NE[1];
    const int* t2 = (const int*)d_in[8]  + NE[2];
    const int* t3 = (const int*)d_in[11] + NE[3];
    int4 ecum4 = make_int4(ec4[0], ec4[1], ec4[2], ec4[3]);
    int4 noff = make_int4(noffA[0], noffA[1], noffA[2], noffA[3]);

    int bs[LVLS], cumB = 0;
    for (int i = 0; i < LVLS; i++) { cumB += (NN[i] + NPB - 1) / NPB; bs[i] = cumB; }
    int4 bstart = make_int4(bs[0], bs[1], bs[2], bs[3]);
    int4 ncnt = make_int4(NN[0], NN[1], NN[2], NN[3]);
    int epb = (cumE4 + cumB - 1) / cumB;

    level_all_k<<<cumB, TPB, SMEM_BYTES>>>(
        (const float*)d_in[0], (const float*)d_in[3],
        (const float*)d_in[6], (const float*)d_in[9],
        t0, t1, t2, t3, ecum4, epb, maskp,
        Mp, cp, bo, gamma, beta, out, bstart, noff, ncnt);

    // 3) fixup the rare unmarked nodes
    fixup_k<<<(cumN + 255) / 256, 256>>>(
        maskp,
        (const float*)d_in[0], (const float*)d_in[3],
        (const float*)d_in[6], (const float*)d_in[9],
        bo, gamma, beta, out, noff, cumN);
}

// round 8
// speedup vs baseline: 2.2448x; 1.0400x over previous
#include <cuda_runtime.h>

#define ND 128
#define HD 256
#define LVLS 4
#define TPB 256
#define PTPB 512          // prep threads
#define NPB 128           // nodes per block tile
#define TOTAL_NODES 52400

typedef unsigned long long ull;

__device__ float g_M[LVLS][ND * ND];    // row-major: M[k][j] = (Wv@Wo)[k][j]
__device__ float g_c[LVLS][ND];         // c = bv@Wo
__device__ unsigned char g_mask[TOTAL_NODES];

__device__ __forceinline__ ull ffma2(ull a, ull b, ull c) {
    ull d;
    asm("fma.rn.f32x2 %0, %1, %2, %3;" : "=l"(d) : "l"(a), "l"(b), "l"(c));
    return d;
}
__device__ __forceinline__ float2 upk(ull v) {
    float2 f;
    asm("mov.b64 {%0,%1}, %2;" : "=f"(f.x), "=f"(f.y) : "l"(v));
    return f;
}
__device__ __forceinline__ ull dup2(float a) {
    ull d;
    asm("mov.b64 %0, {%1,%1};" : "=l"(d) : "f"(a));
    return d;
}
__device__ __forceinline__ int sel4(int4 v, int l) {
    return l == 0 ? v.x : l == 1 ? v.y : l == 2 ? v.z : v.w;
}

// Prep: M = Wv@Wo (row-major), c = bv@Wo, + edge-target mask scatter (hidden
// under the latency-bound Wo stream). Mask is pre-zeroed by a graph memset node.
// Grid = 4 levels x 64 row-groups (2 M-rows each) = 256 blocks x 512 threads.
// 512 thr = 128 cols x 4 t-quarters; per-thread 64 loads in 16-wide batches.
__global__ __launch_bounds__(PTPB)
void prep_all_k(const float* __restrict__ Wv, const float* __restrict__ Wo,
                const float* __restrict__ bv, float* __restrict__ M,
                float* __restrict__ cv,
                const int* __restrict__ t0, const int* __restrict__ t1,
                const int* __restrict__ t2, const int* __restrict__ t3,
                int4 ecum4, int4 noff, unsigned char* __restrict__ mask) {
    __shared__ float wv_s[2 * HD];          // 2 Wv rows
    __shared__ float bv_s[HD];
    __shared__ float part[9 * ND];          // quarters 1..3 x (2 rows + c)

    const int tid = threadIdx.x;
    const int lvl = blockIdx.x >> 6, rg = blockIdx.x & 63;
    const int k0 = rg * 2;
    const float* Wvl = Wv + (size_t)lvl * ND * HD;
    const float* Wol = Wo + (size_t)lvl * HD * ND;
    const int j = tid & 127, th = tid >> 7;  // quarter 0..3

    // --- mark scatter: 1 quarter-edge (int4) per thread, fire-and-forget ---
    {
        int i = blockIdx.x * PTPB + tid;
        if (i < ecum4.w) {
            const int* t; int off, no;
            if (i < ecum4.x)      { t = t0; off = 0;       no = noff.x; }
            else if (i < ecum4.y) { t = t1; off = ecum4.x; no = noff.y; }
            else if (i < ecum4.z) { t = t2; off = ecum4.y; no = noff.z; }
            else                  { t = t3; off = ecum4.z; no = noff.w; }
            int4 v = reinterpret_cast<const int4*>(t)[i - off];
            unsigned char* mb = mask + no;
            mb[v.x] = 1; mb[v.y] = 1; mb[v.z] = 1; mb[v.w] = 1;
        }
    }

    // Stage 2 Wv rows + bv (coalesced)
    if (tid < 2 * HD) wv_s[tid] = Wvl[k0 * HD + tid];
    if (tid < HD) bv_s[tid] = bv[lvl * HD + tid];
    __syncthreads();

    // Stream Wo over my t-quarter in explicit 16-wide batches (branch-free).
    const int tBase = th * (HD / 4);
    float acc0 = 0.f, acc1 = 0.f, accc = 0.f;
    #pragma unroll
    for (int tt = 0; tt < HD / 4; tt += 16) {
        float wo[16];
        #pragma unroll
        for (int u = 0; u < 16; u++)
            wo[u] = Wol[(tBase + tt + u) * ND + j];
        #pragma unroll
        for (int u = 0; u < 16; u++) {
            int t = tBase + tt + u;
            acc0 += wv_s[t] * wo[u];
            acc1 += wv_s[HD + t] * wo[u];
            accc += bv_s[t] * wo[u];
        }
    }

    if (th > 0) {
        float* p = part + (th - 1) * 3 * ND;
        p[0 * ND + j] = acc0;
        p[1 * ND + j] = acc1;
        p[2 * ND + j] = accc;
    }
    __syncthreads();
    if (th == 0) {
        #pragma unroll
        for (int q = 0; q < 3; q++) {
            const float* p = part + q * 3 * ND;
            acc0 += p[0 * ND + j];
            acc1 += p[1 * ND + j];
            accc += p[2 * ND + j];
        }
        float* Ml = M + (size_t)lvl * ND * ND;
        Ml[(k0 + 0) * ND + j] = acc0;
        Ml[(k0 + 1) * ND + j] = acc1;
        if (rg == 0) cv[lvl * ND + j] = accc;
    }
}

// GEMM tile 128x128 + exact-mask residual + LN epilogue.
__global__ __launch_bounds__(TPB)
void level_all_k(const float* __restrict__ n0i, const float* __restrict__ n1i,
                 const float* __restrict__ n2i, const float* __restrict__ n3i,
                 const unsigned char* __restrict__ mask,
                 const float* __restrict__ Mb, const float* __restrict__ cvb,
                 const float* __restrict__ bob, const float* __restrict__ gb,
                 const float* __restrict__ bb, float* __restrict__ out,
                 int4 bstart, int4 noff, int4 ncnt) {
    extern __shared__ float sm[];
    float* M_s = sm;                        // ND*ND  (M[k][j])
    float* A_s = sm + ND * ND;              // NPB*ND (A[node][k])

    const int tid = threadIdx.x;
    const int b = blockIdx.x;

    int lvl, b0;
    if (b < bstart.x)      { lvl = 0; b0 = 0; }
    else if (b < bstart.y) { lvl = 1; b0 = bstart.x; }
    else if (b < bstart.z) { lvl = 2; b0 = bstart.y; }
    else                   { lvl = 3; b0 = bstart.z; }

    const float* nodes = lvl == 0 ? n0i : lvl == 1 ? n1i : lvl == 2 ? n2i : n3i;
    const int N  = sel4(ncnt, lvl);
    const int nO = sel4(noff, lvl);
    const float* Ml = Mb + (size_t)lvl * ND * ND;
    float* outl = out + (size_t)nO * ND;
    const int nodeBase = (b - b0) * NPB;

    // Stage M with float4 (16 LDG.128+STS.128 per thread)
    {
        float4* M_s4 = reinterpret_cast<float4*>(M_s);
        const float4* Ml4 = reinterpret_cast<const float4*>(Ml);
        #pragma unroll
        for (int r = 0; r < 16; r++)
            M_s4[tid + r * TPB] = Ml4[tid + r * TPB];
    }

    // Stage A rows (float4 coalesced; OOB rows zero)
    {
        float4* A_s4 = reinterpret_cast<float4*>(A_s);
        const float4* nodes4 = reinterpret_cast<const float4*>(nodes);
        #pragma unroll
        for (int r = 0; r < 16; r++) {
            int idx = tid + r * TPB;        // 0..4095
            int node = idx >> 5, q = idx & 31;
            int gn = nodeBase + node;
            A_s4[idx] = (gn < N) ? nodes4[gn * 32 + q]
                                 : make_float4(0.f, 0.f, 0.f, 0.f);
        }
    }

    const int tc = tid & 15, tr = tid >> 4;
    const int c0a = tc * 4, c0b = 64 + tc * 4;   // two conflict-free col chunks
    const int nloc = tr * 8;

    // Prefetch my 8 mask bytes (consumed in epilogue; latency hidden by mainloop)
    float mk[8];
    #pragma unroll
    for (int u = 0; u < 8; u++) {
        int gn = nodeBase + nloc + u;
        mk[u] = (gn < N && mask[nO + gn]) ? 1.f : 0.f;
    }
    __syncthreads();

    // Mainloop: C[8 nodes][8 cols] += A[8][k] * M[k][8]
    ull acc[8][4];
    #pragma unroll
    for (int u = 0; u < 8; u++)
        #pragma unroll
        for (int c = 0; c < 4; c++) acc[u][c] = 0ull;

    const float* Ar = A_s + nloc * ND;
    #pragma unroll 2
    for (int kk = 0; kk < ND; kk += 4) {
        float4 a[8];
        #pragma unroll
        for (int u = 0; u < 8; u++)
            a[u] = *reinterpret_cast<const float4*>(Ar + u * ND + kk);
        const float* af = reinterpret_cast<const float*>(a);
        #pragma unroll
        for (int t = 0; t < 4; t++) {
            const float* mrow = M_s + (kk + t) * ND;
            ulonglong2 ma = *reinterpret_cast<const ulonglong2*>(mrow + c0a);
            ulonglong2 mb = *reinterpret_cast<const ulonglong2*>(mrow + c0b);
            #pragma unroll
            for (int u = 0; u < 8; u++) {
                ull av2 = dup2(af[u * 4 + t]);
                acc[u][0] = ffma2(av2, ma.x, acc[u][0]);
                acc[u][1] = ffma2(av2, ma.y, acc[u][1]);
                acc[u][2] = ffma2(av2, mb.x, acc[u][2]);
                acc[u][3] = ffma2(av2, mb.y, acc[u][3]);
            }
        }
    }

    // Per-thread params for my 8 columns
    const float* pb = bob + lvl * ND;
    const float* pc = cvb + lvl * ND;
    const float* pg = gb + lvl * ND;
    const float* pp = bb + lvl * ND;
    float4 boA = *reinterpret_cast<const float4*>(pb + c0a);
    float4 boB = *reinterpret_cast<const float4*>(pb + c0b);
    float4 cvA = *reinterpret_cast<const float4*>(pc + c0a);
    float4 cvB = *reinterpret_cast<const float4*>(pc + c0b);
    float4 gA  = *reinterpret_cast<const float4*>(pg + c0a);
    float4 gB  = *reinterpret_cast<const float4*>(pg + c0b);
    float4 bA  = *reinterpret_cast<const float4*>(pp + c0a);
    float4 bB  = *reinterpret_cast<const float4*>(pp + c0b);

    #pragma unroll
    for (int u = 0; u < 8; u++) {
        int node = nloc + u;
        int gn = nodeBase + node;
        float4 r0 = *reinterpret_cast<const float4*>(A_s + node * ND + c0a);
        float4 r1 = *reinterpret_cast<const float4*>(A_s + node * ND + c0b);
        float m = mk[u];
        float x[8];
        float2 p;
        p = upk(acc[u][0]); x[0] = r0.x + boA.x + m * (p.x + cvA.x);
                            x[1] = r0.y + boA.y + m * (p.y + cvA.y);
        p = upk(acc[u][1]); x[2] = r0.z + boA.z + m * (p.x + cvA.z);
                            x[3] = r0.w + boA.w + m * (p.y + cvA.w);
        p = upk(acc[u][2]); x[4] = r1.x + boB.x + m * (p.x + cvB.x);
                            x[5] = r1.y + boB.y + m * (p.y + cvB.y);
        p = upk(acc[u][3]); x[6] = r1.z + boB.z + m * (p.x + cvB.z);
                            x[7] = r1.w + boB.w + m * (p.y + cvB.w);

        float s = 0.f, s2 = 0.f;
        #pragma unroll
        for (int c = 0; c < 8; c++) { s += x[c]; s2 += x[c] * x[c]; }
        #pragma unroll
        for (int o = 8; o > 0; o >>= 1) {   // reduce over the 16-lane tc group
            s  += __shfl_xor_sync(0xffffffffu, s, o);
            s2 += __shfl_xor_sync(0xffffffffu, s2, o);
        }
        float mu = s * (1.f / 128.f);
        float rs = rsqrtf(s2 * (1.f / 128.f) - mu * mu + 1e-5f);

        if (gn < N) {
            float4 o0, o1;
            o0.x = (x[0] - mu) * rs * gA.x + bA.x;
            o0.y = (x[1] - mu) * rs * gA.y + bA.y;
            o0.z = (x[2] - mu) * rs * gA.z + bA.z;
            o0.w = (x[3] - mu) * rs * gA.w + bA.w;
            o1.x = (x[4] - mu) * rs * gB.x + bB.x;
            o1.y = (x[5] - mu) * rs * gB.y + bB.y;
            o1.z = (x[6] - mu) * rs * gB.z + bB.z;
            o1.w = (x[7] - mu) * rs * gB.w + bB.w;
            float* op = outl + (size_t)gn * ND;
            *reinterpret_cast<float4*>(op + c0a) = o0;
            *reinterpret_cast<float4*>(op + c0b) = o1;
        }
    }
}

static const int SMEM_BYTES = (ND + NPB) * ND * (int)sizeof(float);  // 131072

extern "C" void kernel_launch(void* const* d_in, const int* in_sizes, int n_in,
                              void* d_out, int out_size) {
    (void)n_in; (void)out_size;
    int NN[LVLS], NE[LVLS], noffA[LVLS];
    int cumN = 0;
    for (int i = 0; i < LVLS; i++) {
        NN[i] = in_sizes[i * 3] / ND;
        NE[i] = in_sizes[i * 3 + 2] / 2;
        noffA[i] = cumN;
        cumN += NN[i];
    }
    int ec4[LVLS]; int cumE4 = 0;
    for (int i = 0; i < LVLS; i++) { cumE4 += NE[i] / 4; ec4[i] = cumE4; }

    const float* Wv    = (const float*)d_in[16];
    const float* bv    = (const float*)d_in[17];
    const float* Wo    = (const float*)d_in[20];
    const float* bo    = (const float*)d_in[21];
    const float* gamma = (const float*)d_in[22];
    const float* beta  = (const float*)d_in[23];
    float* out = (float*)d_out;

    unsigned char* maskp = nullptr;
    float* Mp = nullptr;
    float* cp = nullptr;
    cudaGetSymbolAddress((void**)&maskp, g_mask);
    cudaGetSymbolAddress((void**)&Mp, g_M);
    cudaGetSymbolAddress((void**)&cp, g_c);

    cudaFuncSetAttribute(level_all_k, cudaFuncAttributeMaxDynamicSharedMemorySize, SMEM_BYTES);

    // 1) zero mask (graph memset node)
    cudaMemsetAsync(maskp, 0, cumN);

    // 2) prep: M/c for all levels + mask marking (hidden under load latency)
    const int* t0 = (const int*)d_in[2]  + NE[0];
    const int* t1 = (const int*)d_in[5]  + NE[1];
    const int* t2 = (const int*)d_in[8]  + NE[2];
    const int* t3 = (const int*)d_in[11] + NE[3];
    int4 ecum4 = make_int4(ec4[0], ec4[1], ec4[2], ec4[3]);
    int4 noff = make_int4(noffA[0], noffA[1], noffA[2], noffA[3]);
    prep_all_k<<<LVLS * 64, PTPB>>>(Wv, Wo, bv, Mp, cp,
                                    t0, t1, t2, t3, ecum4, noff, maskp);

    // 3) fused level kernel (GEMM + exact mask + LN)
    int bs[LVLS], cumB = 0;
    for (int i = 0; i < LVLS; i++) { cumB += (NN[i] + NPB - 1) / NPB; bs[i] = cumB; }
    int4 bstart = make_int4(bs[0], bs[1], bs[2], bs[3]);
    int4 ncnt = make_int4(NN[0], NN[1], NN[2], NN[3]);
    level_all_k<<<cumB, TPB, SMEM_BYTES>>>(
        (const float*)d_in[0], (const float*)d_in[3],
        (const float*)d_in[6], (const float*)d_in[9],
        maskp, Mp, cp, bo, gamma, beta, out, bstart, noff, ncnt);
}